// round 15
// baseline (speedup 1.0000x reference)
#include <cuda_runtime.h>
#include <cuda_fp16.h>
#include <math.h>
#include <mma.h>

#define TOT 65536
#define BGR 128
#define NPG 512
#define NBINS 16
#define EDG 1048576   // 16*TOT

// ---------------- scratch (__device__ globals; zero-init at load) ----------
// side 1
__device__ int    g_cnt1[TOT];          // zero-maintained
__device__ int    g_start1[TOT+1];
__device__ int    g_cursor1[TOT];
__device__ int    g_bsum1[256];
__device__ int    g_boff1[256];
__device__ int    g_srcs1[EDG];
__device__ float  g_dis1[TOT];
__device__ __half g_h0a[TOT*64];
__device__ __half g_h1a[TOT*64];
// side 2
__device__ int    g_cnt2[TOT];          // zero-maintained
__device__ int    g_start2[TOT+1];
__device__ int    g_cursor2[TOT];
__device__ int    g_bsum2[256];
__device__ int    g_boff2[256];
__device__ int    g_srcs2[EDG];
__device__ float  g_dis2[TOT];
__device__ __half g_h0b[TOT*64];
__device__ __half g_h1b[TOT*64];
// shared tail
__device__ float g_af1[TOT*32];
__device__ float g_af2[TOT*32];
__device__ unsigned g_minu[BGR];
__device__ unsigned g_maxu[BGR];
__device__ float g_hist[BGR*NBINS];     // slots 1..15 = cumulative counts
__device__ float g_ctx1[BGR*32];
__device__ float g_ctx2[BGR*32];
__device__ float g_p1[BGR*32];
__device__ float g_p2[BGR*32];

// ---------------- helpers ---------------------------------------------------
__device__ __forceinline__ unsigned f2o(float f){
    unsigned u = __float_as_uint(f);
    return (u & 0x80000000u) ? ~u : (u | 0x80000000u);
}
__device__ __forceinline__ float o2f(unsigned u){
    return __uint_as_float((u & 0x80000000u) ? (u & 0x7fffffffu) : ~u);
}
// accumulate 8 halves (packed in uint4) into acc[0..7]
__device__ __forceinline__ void add8(float* acc, uint4 v){
    __half2 h; float2 f;
    *(unsigned*)&h = v.x; f = __half22float2(h); acc[0]+=f.x; acc[1]+=f.y;
    *(unsigned*)&h = v.y; f = __half22float2(h); acc[2]+=f.x; acc[3]+=f.y;
    *(unsigned*)&h = v.z; f = __half22float2(h); acc[4]+=f.x; acc[5]+=f.y;
    *(unsigned*)&h = v.w; f = __half22float2(h); acc[6]+=f.x; acc[7]+=f.y;
}
// pack 8 floats (two float4) into uint4 of halves
__device__ __forceinline__ uint4 pack8(float4 v0, float4 v1){
    __half2 ha = __floats2half2_rn(v0.x, v0.y);
    __half2 hb = __floats2half2_rn(v0.z, v0.w);
    __half2 hc = __floats2half2_rn(v1.x, v1.y);
    __half2 hd = __floats2half2_rn(v1.z, v1.w);
    uint4 u;
    u.x = *(unsigned*)&ha; u.y = *(unsigned*)&hb;
    u.z = *(unsigned*)&hc; u.w = *(unsigned*)&hd;
    return u;
}

// ---------------- CSR build (both sides fused via blockIdx.y) ---------------
__global__ void k_count(const int* __restrict__ ei1, const int* __restrict__ ei2,
                        int E){
    int side = blockIdx.y;
    if (blockIdx.x == 0 && side == 0){
        if (threadIdx.x < BGR){ g_minu[threadIdx.x] = 0xFFFFFFFFu; g_maxu[threadIdx.x] = 0u; }
        #pragma unroll
        for (int q = 0; q < (BGR*NBINS)/256; q++)
            g_hist[q*256 + threadIdx.x] = 0.f;
    }
    const int* dst = (side ? ei2 : ei1) + E;
    int* cnt = side ? g_cnt2 : g_cnt1;
    int i = blockIdx.x*256 + threadIdx.x;
    if (i < E) atomicAdd(&cnt[dst[i]], 1);
}

__global__ void k_scan1(){
    int side = blockIdx.y;
    const int* cnt = side ? g_cnt2 : g_cnt1;
    int* start = side ? g_start2 : g_start1;
    int* bsum  = side ? g_bsum2  : g_bsum1;
    __shared__ int s[256];
    int i = blockIdx.x*256 + threadIdx.x;
    int c = cnt[i];
    s[threadIdx.x] = c;
    __syncthreads();
    #pragma unroll
    for (int off = 1; off < 256; off <<= 1){
        int t = (threadIdx.x >= off) ? s[threadIdx.x - off] : 0;
        __syncthreads();
        s[threadIdx.x] += t;
        __syncthreads();
    }
    start[i] = s[threadIdx.x] - c;
    if (threadIdx.x == 255) bsum[blockIdx.x] = s[255];
}

__global__ void k_scan2(){
    int side = blockIdx.x;
    const int* bsum = side ? g_bsum2 : g_bsum1;
    int* boff       = side ? g_boff2 : g_boff1;
    __shared__ int s[256];
    int c = bsum[threadIdx.x];
    s[threadIdx.x] = c;
    __syncthreads();
    #pragma unroll
    for (int off = 1; off < 256; off <<= 1){
        int t = (threadIdx.x >= off) ? s[threadIdx.x - off] : 0;
        __syncthreads();
        s[threadIdx.x] += t;
        __syncthreads();
    }
    boff[threadIdx.x] = s[threadIdx.x] - c;
}

__global__ void k_scan3(int E){
    int side = blockIdx.y;
    int* cnt    = side ? g_cnt2    : g_cnt1;
    int* start  = side ? g_start2  : g_start1;
    int* cursor = side ? g_cursor2 : g_cursor1;
    const int* boff = side ? g_boff2 : g_boff1;
    float* dis  = side ? g_dis2    : g_dis1;
    int i = blockIdx.x*256 + threadIdx.x;
    int st = start[i] + boff[i >> 8];
    start[i]  = st;
    cursor[i] = st;
    float d = (float)cnt[i] + 1.0f;
    dis[i] = rsqrtf(d);
    cnt[i] = 0;                              // restore zero invariant
    if (i == 0) start[TOT] = E;
}

__global__ void k_fill(const int* __restrict__ ei1, const int* __restrict__ ei2,
                       int E){
    int side = blockIdx.y;
    const int* ei = side ? ei2 : ei1;
    const int* src = ei;
    const int* dst = ei + E;
    int* cursor = side ? g_cursor2 : g_cursor1;
    int* srcs   = side ? g_srcs2   : g_srcs1;
    int i = blockIdx.x*256 + threadIdx.x;
    if (i < E){
        int d = dst[i];
        int pos = atomicAdd(&cursor[d], 1);
        srcs[pos] = src[i];
    }
}

// ------ dense GEMM via fp16 wmma: H0 = fp16((X @ W) * dis[row]), both sides -
// src_sel = 0: X fp32 from args. src_sel = 1: X fp16 = g_h1a/g_h1b.
template<int K, int M>
__global__ void __launch_bounds__(256) k_gemm(const float* __restrict__ Xa,
                                              const float* __restrict__ Xb,
                                              const float* __restrict__ W,
                                              int src_sel){
    using namespace nvcuda;
    constexpr int R   = 2048 / M;     // 32 (M=64) or 64 (M=32)
    constexpr int CT  = M / 16;
    constexpr int KP2 = 72;           // half stride; 16B-aligned rows, conflict-free ldmatrix
    constexpr int MP2 = M + 8;
    __shared__ __align__(16) __half sX[R * KP2];
    __shared__ __align__(16) __half sW[64 * MP2];
    __shared__ __align__(16) float  sO[2048];

    int side = blockIdx.y;
    const float* dis = side ? g_dis2 : g_dis1;
    __half* H0       = side ? g_h0b  : g_h0a;

    int row0 = blockIdx.x * R;
    int warp = threadIdx.x >> 5;
    int tr = warp / CT, tc = warp % CT;

    wmma::fragment<wmma::accumulator, 16, 16, 16, float> c;
    wmma::fill_fragment(c, 0.0f);

    for (int kc = 0; kc < K; kc += 64){
        // stage X (64 cols) as fp16
        if (src_sel){
            const __half* Xh = side ? g_h1b : g_h1a;      // K == 64 here
            for (int i = threadIdx.x; i < R*8; i += 256){
                int r = i >> 3, cc = i & 7;
                *(uint4*)(sX + r*KP2 + cc*8) =
                    ((const uint4*)(Xh + (size_t)(row0 + r) * K))[cc];
            }
        } else {
            const float* Xf = side ? Xb : Xa;
            for (int i = threadIdx.x; i < R*8; i += 256){
                int r = i >> 3, cc = i & 7;
                const float4* p = (const float4*)(Xf + (size_t)(row0 + r)*K + kc + cc*8);
                *(uint4*)(sX + r*KP2 + cc*8) = pack8(p[0], p[1]);
            }
        }
        // stage W (64 x M) as fp16
        for (int i = threadIdx.x; i < 64*(M/8); i += 256){
            int r = i / (M/8), cc = i % (M/8);
            const float4* p = (const float4*)(W + (size_t)(kc + r)*M + cc*8);
            *(uint4*)(sW + r*MP2 + cc*8) = pack8(p[0], p[1]);
        }
        __syncthreads();
        #pragma unroll
        for (int k0 = 0; k0 < 64; k0 += 16){
            wmma::fragment<wmma::matrix_a, 16, 16, 16, __half, wmma::row_major> a;
            wmma::fragment<wmma::matrix_b, 16, 16, 16, __half, wmma::row_major> bf;
            wmma::load_matrix_sync(a,  sX + tr*16*KP2 + k0, KP2);
            wmma::load_matrix_sync(bf, sW + k0*MP2 + tc*16, MP2);
            wmma::mma_sync(c, a, bf, c);
        }
        __syncthreads();
    }

    wmma::store_matrix_sync(sO + tr*16*M + tc*16, c, M, wmma::mem_row_major);
    __syncthreads();
    constexpr int MH = M / 8;
    for (int i = threadIdx.x; i < R * MH; i += 256){
        int r = i / MH;
        float d = dis[row0 + r];
        float4 v0 = ((float4*)sO)[i*2];
        float4 v1 = ((float4*)sO)[i*2 + 1];
        v0.x*=d; v0.y*=d; v0.z*=d; v0.w*=d;
        v1.x*=d; v1.y*=d; v1.z*=d; v1.w*=d;
        ((uint4*)(H0 + (size_t)row0 * M))[i] = pack8(v0, v1);
    }
}

// ------ fused gather+finalize, both sides: out = relu?((Σ+self)*dis + b) ----
// 4-way unrolled edge loop for MLP (h0 rows are L2-resident; lat ~240cyc).
template<int F, bool RELU, bool LAST>
__global__ void __launch_bounds__(256) k_gf(const float* __restrict__ bias){
    constexpr int G  = F/8;
    constexpr int SH = (F==64) ? 3 : 2;
    int side = blockIdx.y;
    const __half* h0  = side ? g_h0b    : g_h0a;
    const int* srcs   = side ? g_srcs2  : g_srcs1;
    const int* start  = side ? g_start2 : g_start1;
    const float* dis  = side ? g_dis2   : g_dis1;

    int t   = blockIdx.x*256 + threadIdx.x;
    int row = t >> SH;
    int j   = t & (G-1);

    float acc[8] = {};
    add8(acc, ((const uint4*)(h0 + (size_t)row*F))[j]);      // self term

    int e  = start[row];
    int e1 = start[row+1];
    for (; e + 3 < e1; e += 4){
        int sa = __ldg(&srcs[e]);
        int sb = __ldg(&srcs[e+1]);
        int sc = __ldg(&srcs[e+2]);
        int sd = __ldg(&srcs[e+3]);
        uint4 va = ((const uint4*)(h0 + (size_t)sa*F))[j];
        uint4 vb = ((const uint4*)(h0 + (size_t)sb*F))[j];
        uint4 vc = ((const uint4*)(h0 + (size_t)sc*F))[j];
        uint4 vd = ((const uint4*)(h0 + (size_t)sd*F))[j];
        add8(acc, va);
        add8(acc, vb);
        add8(acc, vc);
        add8(acc, vd);
    }
    for (; e < e1; e++){
        int sa = __ldg(&srcs[e]);
        add8(acc, ((const uint4*)(h0 + (size_t)sa*F))[j]);
    }

    float di = dis[row];
    float4 b0 = ((const float4*)bias)[2*j];
    float4 b1 = ((const float4*)bias)[2*j + 1];
    float4 o0, o1;
    o0.x = acc[0]*di + b0.x; o0.y = acc[1]*di + b0.y;
    o0.z = acc[2]*di + b0.z; o0.w = acc[3]*di + b0.w;
    o1.x = acc[4]*di + b1.x; o1.y = acc[5]*di + b1.y;
    o1.z = acc[6]*di + b1.z; o1.w = acc[7]*di + b1.w;
    if (RELU){
        o0.x = fmaxf(o0.x,0.f); o0.y = fmaxf(o0.y,0.f);
        o0.z = fmaxf(o0.z,0.f); o0.w = fmaxf(o0.w,0.f);
        o1.x = fmaxf(o1.x,0.f); o1.y = fmaxf(o1.y,0.f);
        o1.z = fmaxf(o1.z,0.f); o1.w = fmaxf(o1.w,0.f);
    }
    if (LAST){
        float* out = side ? g_af2 : g_af1;
        ((float4*)out)[2*t]     = o0;
        ((float4*)out)[2*t + 1] = o1;
    } else {
        __half* out = side ? g_h1b : g_h1a;
        ((uint4*)out)[t] = pack8(o0, o1);
    }
}

// ---------------- histogram (fp16 wmma; af converted at smem staging) -------
#define LDH 40   // halves; 80-byte row stride, 16B aligned

__device__ __forceinline__ void stage_half_tiles(__half* sA, __half* sB,
                                                 const float* A, const float* Bp){
    for (int i = threadIdx.x; i < 128*4; i += 256){
        int r = i >> 2, c4 = i & 3;
        const float4* pa = (const float4*)(A + (size_t)r*32);
        *(uint4*)(sA + r*LDH + c4*8) = pack8(pa[c4*2], pa[c4*2 + 1]);
        const float4* pb = (const float4*)(Bp + (size_t)r*32);
        *(uint4*)(sB + r*LDH + c4*8) = pack8(pb[c4*2], pb[c4*2 + 1]);
    }
}

// pass A: fp16 dot min/max only (no stores)
__global__ void __launch_bounds__(256) k_dotA(){
    using namespace nvcuda;
    __shared__ __align__(16) __half sA[128*LDH];
    __shared__ __align__(16) __half sB[128*LDH];
    int b    = blockIdx.x >> 4;
    int tile = blockIdx.x & 15;
    int i0 = (tile >> 2) * 128, j0 = (tile & 3) * 128;
    stage_half_tiles(sA, sB,
                     g_af1 + ((size_t)b*NPG + i0)*32,
                     g_af2 + ((size_t)b*NPG + j0)*32);
    __syncthreads();

    int warp = threadIdx.x >> 5;
    float lmin = INFINITY, lmax = -INFINITY;

    #pragma unroll
    for (int tc = 0; tc < 8; tc++){
        wmma::fragment<wmma::accumulator, 16, 16, 16, float> c;
        wmma::fill_fragment(c, 0.0f);
        #pragma unroll
        for (int k0 = 0; k0 < 32; k0 += 16){
            wmma::fragment<wmma::matrix_a, 16, 16, 16, __half, wmma::row_major> a;
            wmma::fragment<wmma::matrix_b, 16, 16, 16, __half, wmma::col_major> bf;
            wmma::load_matrix_sync(a,  sA + warp*16*LDH + k0, LDH);
            wmma::load_matrix_sync(bf, sB + tc*16*LDH  + k0, LDH);
            wmma::mma_sync(c, a, bf, c);
        }
        #pragma unroll
        for (int q = 0; q < c.num_elements; q++){
            lmin = fminf(lmin, c.x[q]); lmax = fmaxf(lmax, c.x[q]);
        }
    }

    #pragma unroll
    for (int off=16; off; off>>=1){
        lmin = fminf(lmin, __shfl_down_sync(0xffffffffu, lmin, off));
        lmax = fmaxf(lmax, __shfl_down_sync(0xffffffffu, lmax, off));
    }
    __shared__ float wmn[8], wmx[8];
    if ((threadIdx.x & 31) == 0){ wmn[warp] = lmin; wmx[warp] = lmax; }
    __syncthreads();
    if (threadIdx.x == 0){
        float m = wmn[0], M = wmx[0];
        for (int q=1;q<8;q++){ m = fminf(m, wmn[q]); M = fmaxf(M, wmx[q]); }
        atomicMin(&g_minu[b], f2o(m));
        atomicMax(&g_maxu[b], f2o(M));
    }
}

// pass B: recompute identical fp16 dots, thresholds per-block, bin in-register
__global__ void __launch_bounds__(256) k_dotB(){
    using namespace nvcuda;
    __shared__ __align__(16) __half sA[128*LDH];
    __shared__ __align__(16) __half sB[128*LDH];
    __shared__ float sth[15];
    __shared__ float scnt[15];
    int b    = blockIdx.x >> 4;
    int tile = blockIdx.x & 15;
    int i0 = (tile >> 2) * 128, j0 = (tile & 3) * 128;
    stage_half_tiles(sA, sB,
                     g_af1 + ((size_t)b*NPG + i0)*32,
                     g_af2 + ((size_t)b*NPG + j0)*32);
    if (threadIdx.x < 15){
        scnt[threadIdx.x] = 0.f;
        float tmin = o2f(g_minu[b]), tmax = o2f(g_maxu[b]);
        float mn = 1.0f/(1.0f + expf(-tmin));
        float mx = 1.0f/(1.0f + expf(-tmax));
        float rng = (mx > mn) ? (mx - mn) : 1.0f;
        const float PINF = __int_as_float(0x7f800000);
        float p = mn + rng * ((threadIdx.x + 1) * (1.0f/16.0f));
        float thr;
        if (p <= 0.0f)      thr = -PINF;
        else if (p >= 1.0f) thr =  PINF;
        else                thr = logf(p / (1.0f - p));
        sth[threadIdx.x] = thr;
    }
    __syncthreads();

    float th[15];
    #pragma unroll
    for (int k=0;k<15;k++) th[k] = sth[k];

    int warp = threadIdx.x >> 5;
    float cnt[15] = {};

    #pragma unroll
    for (int tc = 0; tc < 8; tc++){
        wmma::fragment<wmma::accumulator, 16, 16, 16, float> c;
        wmma::fill_fragment(c, 0.0f);
        #pragma unroll
        for (int k0 = 0; k0 < 32; k0 += 16){
            wmma::fragment<wmma::matrix_a, 16, 16, 16, __half, wmma::row_major> a;
            wmma::fragment<wmma::matrix_b, 16, 16, 16, __half, wmma::col_major> bf;
            wmma::load_matrix_sync(a,  sA + warp*16*LDH + k0, LDH);
            wmma::load_matrix_sync(bf, sB + tc*16*LDH  + k0, LDH);
            wmma::mma_sync(c, a, bf, c);
        }
        #pragma unroll
        for (int q = 0; q < c.num_elements; q++){
            float v = c.x[q];
            #pragma unroll
            for (int k=0;k<15;k++)
                cnt[k] += (v >= th[k]) ? 1.0f : 0.0f;
        }
    }

    #pragma unroll
    for (int off=16; off; off>>=1)
        #pragma unroll
        for (int k=0;k<15;k++)
            cnt[k] += __shfl_down_sync(0xffffffffu, cnt[k], off);
    if ((threadIdx.x & 31) == 0)
        #pragma unroll
        for (int k=0;k<15;k++)
            atomicAdd(&scnt[k], cnt[k]);
    __syncthreads();
    if (threadIdx.x < 15)
        atomicAdd(&g_hist[b*NBINS + threadIdx.x + 1], scnt[threadIdx.x]);
}

// ---------------- attention pooling (both sides fused) ----------------------
__global__ void __launch_bounds__(256) k_att1(const float* __restrict__ attW){
    int side = blockIdx.y;
    const float* af = side ? g_af2  : g_af1;
    float* ctx      = side ? g_ctx2 : g_ctx1;
    int b = blockIdx.x;
    __shared__ float sm[8*32], smean[32];
    int f = threadIdx.x & 31, grp = threadIdx.x >> 5;
    const float* base = af + (size_t)b*NPG*32;
    float acc = 0.f;
    for (int n = grp; n < NPG; n += 8) acc += base[n*32 + f];
    sm[grp*32 + f] = acc;
    __syncthreads();
    if (threadIdx.x < 32){
        float m = 0.f;
        for (int g=0; g<8; g++) m += sm[g*32 + threadIdx.x];
        smean[threadIdx.x] = m * (1.0f/512.0f);
    }
    __syncthreads();
    if (threadIdx.x < 32){
        int j = threadIdx.x;
        float t = 0.f;
        for (int ff=0; ff<32; ff++) t += smean[ff]*attW[ff*32 + j];
        ctx[b*32 + j] = tanhf(t);
    }
}

__global__ void __launch_bounds__(256) k_att2(){
    int side = blockIdx.y;
    const float* af  = side ? g_af2  : g_af1;
    const float* ctx = side ? g_ctx2 : g_ctx1;
    float* gp        = side ? g_p2   : g_p1;
    int b = blockIdx.x;
    __shared__ float st[32];
    __shared__ float ssig[NPG];
    __shared__ float sm[8*32];
    if (threadIdx.x < 32) st[threadIdx.x] = ctx[b*32 + threadIdx.x];
    __syncthreads();
    const float* base = af + (size_t)b*NPG*32;
    for (int n = threadIdx.x; n < NPG; n += 256){
        float d = 0.f;
        #pragma unroll
        for (int q=0; q<8; q++){
            float4 v = *(const float4*)(base + n*32 + q*4);
            d += v.x*st[q*4] + v.y*st[q*4+1] + v.z*st[q*4+2] + v.w*st[q*4+3];
        }
        ssig[n] = 1.0f/(1.0f + __expf(-d));
    }
    __syncthreads();
    int f = threadIdx.x & 31, grp = threadIdx.x >> 5;
    float acc = 0.f;
    for (int n = grp; n < NPG; n += 8) acc += base[n*32 + f] * ssig[n];
    sm[grp*32 + f] = acc;
    __syncthreads();
    if (threadIdx.x < 32){
        float s = 0.f;
        for (int g=0; g<8; g++) s += sm[g*32 + threadIdx.x];
        gp[b*32 + threadIdx.x] = s;
    }
}

// ---------------- NTN + head -----------------------------------------------
__global__ void __launch_bounds__(512) k_ntn(const float* __restrict__ ntnW,
                                             const float* __restrict__ ntnV,
                                             const float* __restrict__ ntnb,
                                             const float* __restrict__ fc1W,
                                             const float* __restrict__ fc1b,
                                             const float* __restrict__ scW,
                                             const float* __restrict__ scb,
                                             float* __restrict__ out){
    int b = blockIdx.x;
    __shared__ float sp1[32], sp2[32], sred[512], sfeat[32], sh[16];
    int tid = threadIdx.x;
    if (tid < 32){ sp1[tid] = g_p1[b*32+tid]; sp2[tid] = g_p2[b*32+tid]; }
    __syncthreads();
    int j = tid >> 4, k = tid & 15;
    float acc = 0.f;
    #pragma unroll 8
    for (int i=0; i<32; i++) acc += sp1[i] * ntnW[i*512 + j*16 + k];
    sred[tid] = acc * sp2[j];
    __syncthreads();
    for (int off=256; off>=16; off>>=1){
        if (tid < off) sred[tid] += sred[tid+off];
        __syncthreads();
    }
    if (tid < 16){
        float blk = 0.f;
        for (int i=0; i<32; i++)
            blk += sp1[i]*ntnV[tid*64 + i] + sp2[i]*ntnV[tid*64 + 32 + i];
        sfeat[tid] = fmaxf(sred[tid] + blk + ntnb[tid], 0.f);
        float ck  = (tid==0)  ? 262144.0f : g_hist[b*NBINS + tid];
        float ck1 = (tid==15) ? 0.0f      : g_hist[b*NBINS + tid + 1];
        sfeat[16 + tid] = (ck - ck1) * (1.0f/262144.0f);
    }
    __syncthreads();
    if (tid < 16){
        float h = fc1b[tid];
        for (int m=0; m<32; m++) h += sfeat[m]*fc1W[m*16 + tid];
        sh[tid] = fmaxf(h, 0.f);
    }
    __syncthreads();
    if (tid == 0){
        float o = scb[0];
        for (int n=0; n<16; n++) o += sh[n]*scW[n];
        out[b] = 1.0f/(1.0f + expf(-o));
    }
}

// ---------------- launch ----------------------------------------------------
extern "C" void kernel_launch(void* const* d_in, const int* in_sizes, int n_in,
                              void* d_out, int out_size) {
    const float* x1   = (const float*)d_in[0];
    const float* x2   = (const float*)d_in[1];
    const int*   ei1  = (const int*)d_in[2];
    const int*   ei2  = (const int*)d_in[3];
    const float* W1   = (const float*)d_in[6];
    const float* b1   = (const float*)d_in[7];
    const float* W2   = (const float*)d_in[8];
    const float* b2   = (const float*)d_in[9];
    const float* W3   = (const float*)d_in[10];
    const float* b3   = (const float*)d_in[11];
    const float* attW = (const float*)d_in[12];
    const float* ntnW = (const float*)d_in[13];
    const float* ntnV = (const float*)d_in[14];
    const float* ntnb = (const float*)d_in[15];
    const float* fc1W = (const float*)d_in[16];
    const float* fc1b = (const float*)d_in[17];
    const float* scW  = (const float*)d_in[18];
    const float* scb  = (const float*)d_in[19];
    float* out = (float*)d_out;
    int E = in_sizes[2] / 2;

    // CSR build, both sides fused (k_count also inits histogram state)
    k_count<<<dim3((E+255)/256, 2), 256>>>(ei1, ei2, E);
    k_scan1<<<dim3(256, 2), 256>>>();
    k_scan2<<<2, 256>>>();
    k_scan3<<<dim3(TOT/256, 2), 256>>>(E);
    k_fill<<<dim3((E+255)/256, 2), 256>>>(ei1, ei2, E);

    // GCN stack, both sides fused (fp16 wmma GEMM; h0/h1 fp16)
    k_gemm<128,64><<<dim3(TOT/32, 2), 256>>>(x1, x2, W1, 0);
    k_gf<64,true,false><<<dim3(TOT*8/256, 2), 256>>>(b1);

    k_gemm<64,64><<<dim3(TOT/32, 2), 256>>>(nullptr, nullptr, W2, 1);
    k_gf<64,true,false><<<dim3(TOT*8/256, 2), 256>>>(b2);

    k_gemm<64,32><<<dim3(TOT/64, 2), 256>>>(nullptr, nullptr, W3, 1);
    k_gf<32,false,true><<<dim3(TOT*4/256, 2), 256>>>(b3);

    // histogram chain (fp16 wmma, thresholds inside dotB)
    k_dotA<<<BGR*16, 256>>>();
    k_dotB<<<BGR*16, 256>>>();

    // attention, both sides fused
    k_att1<<<dim3(BGR, 2), 256>>>(attW);
    k_att2<<<dim3(BGR, 2), 256>>>();

    k_ntn<<<BGR, 512>>>(ntnW, ntnV, ntnb, fc1W, fc1b, scW, scb, out);
}

// round 16
// speedup vs baseline: 1.0149x; 1.0149x over previous
#include <cuda_runtime.h>
#include <cuda_fp16.h>
#include <math.h>
#include <mma.h>

#define TOT 65536
#define BGR 128
#define NPG 512
#define NBINS 16
#define EDG 1048576   // 16*TOT

// ---------------- scratch (__device__ globals; zero-init at load) ----------
// side 1
__device__ int    g_cnt1[TOT];          // zero-maintained
__device__ int    g_start1[TOT+1];
__device__ int    g_cursor1[TOT];
__device__ int    g_bsum1[256];
__device__ int    g_boff1[256];
__device__ int    g_srcs1[EDG];
__device__ float  g_dis1[TOT];
__device__ __half g_h0a[TOT*64];
__device__ __half g_h1a[TOT*64];
// side 2
__device__ int    g_cnt2[TOT];          // zero-maintained
__device__ int    g_start2[TOT+1];
__device__ int    g_cursor2[TOT];
__device__ int    g_bsum2[256];
__device__ int    g_boff2[256];
__device__ int    g_srcs2[EDG];
__device__ float  g_dis2[TOT];
__device__ __half g_h0b[TOT*64];
__device__ __half g_h1b[TOT*64];
// shared tail
__device__ float g_af1[TOT*32];
__device__ float g_af2[TOT*32];
__device__ unsigned g_minu[BGR];
__device__ unsigned g_maxu[BGR];
__device__ float g_hist[BGR*NBINS];     // slots 1..15 = cumulative counts
__device__ float g_ctx1[BGR*32];
__device__ float g_ctx2[BGR*32];
__device__ float g_p1[BGR*32];
__device__ float g_p2[BGR*32];

// ---------------- helpers ---------------------------------------------------
__device__ __forceinline__ unsigned f2o(float f){
    unsigned u = __float_as_uint(f);
    return (u & 0x80000000u) ? ~u : (u | 0x80000000u);
}
__device__ __forceinline__ float o2f(unsigned u){
    return __uint_as_float((u & 0x80000000u) ? (u & 0x7fffffffu) : ~u);
}
// accumulate 8 halves (packed in uint4) into acc[0..7]
__device__ __forceinline__ void add8(float* acc, uint4 v){
    __half2 h; float2 f;
    *(unsigned*)&h = v.x; f = __half22float2(h); acc[0]+=f.x; acc[1]+=f.y;
    *(unsigned*)&h = v.y; f = __half22float2(h); acc[2]+=f.x; acc[3]+=f.y;
    *(unsigned*)&h = v.z; f = __half22float2(h); acc[4]+=f.x; acc[5]+=f.y;
    *(unsigned*)&h = v.w; f = __half22float2(h); acc[6]+=f.x; acc[7]+=f.y;
}
// pack 8 floats (two float4) into uint4 of halves
__device__ __forceinline__ uint4 pack8(float4 v0, float4 v1){
    __half2 ha = __floats2half2_rn(v0.x, v0.y);
    __half2 hb = __floats2half2_rn(v0.z, v0.w);
    __half2 hc = __floats2half2_rn(v1.x, v1.y);
    __half2 hd = __floats2half2_rn(v1.z, v1.w);
    uint4 u;
    u.x = *(unsigned*)&ha; u.y = *(unsigned*)&hb;
    u.z = *(unsigned*)&hc; u.w = *(unsigned*)&hd;
    return u;
}

// ---------------- CSR build (both sides fused via blockIdx.y) ---------------
__global__ void k_count(const int* __restrict__ ei1, const int* __restrict__ ei2,
                        int E){
    int side = blockIdx.y;
    if (blockIdx.x == 0 && side == 0){
        if (threadIdx.x < BGR){ g_minu[threadIdx.x] = 0xFFFFFFFFu; g_maxu[threadIdx.x] = 0u; }
        #pragma unroll
        for (int q = 0; q < (BGR*NBINS)/256; q++)
            g_hist[q*256 + threadIdx.x] = 0.f;
    }
    const int* dst = (side ? ei2 : ei1) + E;
    int* cnt = side ? g_cnt2 : g_cnt1;
    int i = blockIdx.x*256 + threadIdx.x;
    if (i < E) atomicAdd(&cnt[dst[i]], 1);
}

__global__ void k_scan1(){
    int side = blockIdx.y;
    const int* cnt = side ? g_cnt2 : g_cnt1;
    int* start = side ? g_start2 : g_start1;
    int* bsum  = side ? g_bsum2  : g_bsum1;
    __shared__ int s[256];
    int i = blockIdx.x*256 + threadIdx.x;
    int c = cnt[i];
    s[threadIdx.x] = c;
    __syncthreads();
    #pragma unroll
    for (int off = 1; off < 256; off <<= 1){
        int t = (threadIdx.x >= off) ? s[threadIdx.x - off] : 0;
        __syncthreads();
        s[threadIdx.x] += t;
        __syncthreads();
    }
    start[i] = s[threadIdx.x] - c;
    if (threadIdx.x == 255) bsum[blockIdx.x] = s[255];
}

__global__ void k_scan2(){
    int side = blockIdx.x;
    const int* bsum = side ? g_bsum2 : g_bsum1;
    int* boff       = side ? g_boff2 : g_boff1;
    __shared__ int s[256];
    int c = bsum[threadIdx.x];
    s[threadIdx.x] = c;
    __syncthreads();
    #pragma unroll
    for (int off = 1; off < 256; off <<= 1){
        int t = (threadIdx.x >= off) ? s[threadIdx.x - off] : 0;
        __syncthreads();
        s[threadIdx.x] += t;
        __syncthreads();
    }
    boff[threadIdx.x] = s[threadIdx.x] - c;
}

__global__ void k_scan3(int E){
    int side = blockIdx.y;
    int* cnt    = side ? g_cnt2    : g_cnt1;
    int* start  = side ? g_start2  : g_start1;
    int* cursor = side ? g_cursor2 : g_cursor1;
    const int* boff = side ? g_boff2 : g_boff1;
    float* dis  = side ? g_dis2    : g_dis1;
    int i = blockIdx.x*256 + threadIdx.x;
    int st = start[i] + boff[i >> 8];
    start[i]  = st;
    cursor[i] = st;
    float d = (float)cnt[i] + 1.0f;
    dis[i] = rsqrtf(d);
    cnt[i] = 0;                              // restore zero invariant
    if (i == 0) start[TOT] = E;
}

__global__ void k_fill(const int* __restrict__ ei1, const int* __restrict__ ei2,
                       int E){
    int side = blockIdx.y;
    const int* ei = side ? ei2 : ei1;
    const int* src = ei;
    const int* dst = ei + E;
    int* cursor = side ? g_cursor2 : g_cursor1;
    int* srcs   = side ? g_srcs2   : g_srcs1;
    int i = blockIdx.x*256 + threadIdx.x;
    if (i < E){
        int d = dst[i];
        int pos = atomicAdd(&cursor[d], 1);
        srcs[pos] = src[i];
    }
}

// ------ dense GEMM via fp16 wmma: H0 = fp16((X @ W) * dis[row]), both sides -
// src_sel = 0: X fp32 from args. src_sel = 1: X fp16 = g_h1a/g_h1b.
template<int K, int M>
__global__ void __launch_bounds__(256) k_gemm(const float* __restrict__ Xa,
                                              const float* __restrict__ Xb,
                                              const float* __restrict__ W,
                                              int src_sel){
    using namespace nvcuda;
    constexpr int R   = 2048 / M;     // 32 (M=64) or 64 (M=32)
    constexpr int CT  = M / 16;
    constexpr int KP2 = 72;           // half stride; 16B-aligned rows, conflict-free ldmatrix
    constexpr int MP2 = M + 8;
    __shared__ __align__(16) __half sX[R * KP2];
    __shared__ __align__(16) __half sW[64 * MP2];
    __shared__ __align__(16) float  sO[2048];

    int side = blockIdx.y;
    const float* dis = side ? g_dis2 : g_dis1;
    __half* H0       = side ? g_h0b  : g_h0a;

    int row0 = blockIdx.x * R;
    int warp = threadIdx.x >> 5;
    int tr = warp / CT, tc = warp % CT;

    wmma::fragment<wmma::accumulator, 16, 16, 16, float> c;
    wmma::fill_fragment(c, 0.0f);

    for (int kc = 0; kc < K; kc += 64){
        // stage X (64 cols) as fp16
        if (src_sel){
            const __half* Xh = side ? g_h1b : g_h1a;      // K == 64 here
            for (int i = threadIdx.x; i < R*8; i += 256){
                int r = i >> 3, cc = i & 7;
                *(uint4*)(sX + r*KP2 + cc*8) =
                    ((const uint4*)(Xh + (size_t)(row0 + r) * K))[cc];
            }
        } else {
            const float* Xf = side ? Xb : Xa;
            for (int i = threadIdx.x; i < R*8; i += 256){
                int r = i >> 3, cc = i & 7;
                const float4* p = (const float4*)(Xf + (size_t)(row0 + r)*K + kc + cc*8);
                *(uint4*)(sX + r*KP2 + cc*8) = pack8(p[0], p[1]);
            }
        }
        // stage W (64 x M) as fp16
        for (int i = threadIdx.x; i < 64*(M/8); i += 256){
            int r = i / (M/8), cc = i % (M/8);
            const float4* p = (const float4*)(W + (size_t)(kc + r)*M + cc*8);
            *(uint4*)(sW + r*MP2 + cc*8) = pack8(p[0], p[1]);
        }
        __syncthreads();
        #pragma unroll
        for (int k0 = 0; k0 < 64; k0 += 16){
            wmma::fragment<wmma::matrix_a, 16, 16, 16, __half, wmma::row_major> a;
            wmma::fragment<wmma::matrix_b, 16, 16, 16, __half, wmma::row_major> bf;
            wmma::load_matrix_sync(a,  sX + tr*16*KP2 + k0, KP2);
            wmma::load_matrix_sync(bf, sW + k0*MP2 + tc*16, MP2);
            wmma::mma_sync(c, a, bf, c);
        }
        __syncthreads();
    }

    wmma::store_matrix_sync(sO + tr*16*M + tc*16, c, M, wmma::mem_row_major);
    __syncthreads();
    constexpr int MH = M / 8;
    for (int i = threadIdx.x; i < R * MH; i += 256){
        int r = i / MH;
        float d = dis[row0 + r];
        float4 v0 = ((float4*)sO)[i*2];
        float4 v1 = ((float4*)sO)[i*2 + 1];
        v0.x*=d; v0.y*=d; v0.z*=d; v0.w*=d;
        v1.x*=d; v1.y*=d; v1.z*=d; v1.w*=d;
        ((uint4*)(H0 + (size_t)row0 * M))[i] = pack8(v0, v1);
    }
}

// ------ fused gather+finalize, both sides: out = relu?((Σ+self)*dis + b) ----
template<int F, bool RELU, bool LAST>
__global__ void __launch_bounds__(256) k_gf(const float* __restrict__ bias){
    constexpr int G  = F/8;
    constexpr int SH = (F==64) ? 3 : 2;
    int side = blockIdx.y;
    const __half* h0  = side ? g_h0b    : g_h0a;
    const int* srcs   = side ? g_srcs2  : g_srcs1;
    const int* start  = side ? g_start2 : g_start1;
    const float* dis  = side ? g_dis2   : g_dis1;

    int t   = blockIdx.x*256 + threadIdx.x;
    int row = t >> SH;
    int j   = t & (G-1);

    float acc[8] = {};
    add8(acc, ((const uint4*)(h0 + (size_t)row*F))[j]);      // self term

    int e  = start[row];
    int e1 = start[row+1];
    for (; e + 1 < e1; e += 2){
        int sa = __ldg(&srcs[e]);
        int sb = __ldg(&srcs[e+1]);
        uint4 va = ((const uint4*)(h0 + (size_t)sa*F))[j];
        uint4 vb = ((const uint4*)(h0 + (size_t)sb*F))[j];
        add8(acc, va);
        add8(acc, vb);
    }
    if (e < e1){
        int sa = __ldg(&srcs[e]);
        add8(acc, ((const uint4*)(h0 + (size_t)sa*F))[j]);
    }

    float di = dis[row];
    float4 b0 = ((const float4*)bias)[2*j];
    float4 b1 = ((const float4*)bias)[2*j + 1];
    float4 o0, o1;
    o0.x = acc[0]*di + b0.x; o0.y = acc[1]*di + b0.y;
    o0.z = acc[2]*di + b0.z; o0.w = acc[3]*di + b0.w;
    o1.x = acc[4]*di + b1.x; o1.y = acc[5]*di + b1.y;
    o1.z = acc[6]*di + b1.z; o1.w = acc[7]*di + b1.w;
    if (RELU){
        o0.x = fmaxf(o0.x,0.f); o0.y = fmaxf(o0.y,0.f);
        o0.z = fmaxf(o0.z,0.f); o0.w = fmaxf(o0.w,0.f);
        o1.x = fmaxf(o1.x,0.f); o1.y = fmaxf(o1.y,0.f);
        o1.z = fmaxf(o1.z,0.f); o1.w = fmaxf(o1.w,0.f);
    }
    if (LAST){
        float* out = side ? g_af2 : g_af1;
        ((float4*)out)[2*t]     = o0;
        ((float4*)out)[2*t + 1] = o1;
    } else {
        __half* out = side ? g_h1b : g_h1a;
        ((uint4*)out)[t] = pack8(o0, o1);
    }
}

// ---------------- histogram + attention (fused heterogeneous launches) ------
#define LDH 40   // halves; 80-byte row stride, 16B aligned
#define DOT_BLOCKS (BGR*16)

__device__ __forceinline__ void stage_half_tiles(__half* sA, __half* sB,
                                                 const float* A, const float* Bp){
    for (int i = threadIdx.x; i < 128*4; i += 256){
        int r = i >> 2, c4 = i & 3;
        const float4* pa = (const float4*)(A + (size_t)r*32);
        *(uint4*)(sA + r*LDH + c4*8) = pack8(pa[c4*2], pa[c4*2 + 1]);
        const float4* pb = (const float4*)(Bp + (size_t)r*32);
        *(uint4*)(sB + r*LDH + c4*8) = pack8(pb[c4*2], pb[c4*2 + 1]);
    }
}

// attention phase 1: ctx = tanh(mean(af) @ attW)
__device__ __forceinline__ void att1_body(int side, int b,
                                          const float* __restrict__ attW){
    const float* af = side ? g_af2  : g_af1;
    float* ctx      = side ? g_ctx2 : g_ctx1;
    __shared__ float sm[8*32], smean[32];
    int f = threadIdx.x & 31, grp = threadIdx.x >> 5;
    const float* base = af + (size_t)b*NPG*32;
    float acc = 0.f;
    for (int n = grp; n < NPG; n += 8) acc += base[n*32 + f];
    sm[grp*32 + f] = acc;
    __syncthreads();
    if (threadIdx.x < 32){
        float m = 0.f;
        for (int g=0; g<8; g++) m += sm[g*32 + threadIdx.x];
        smean[threadIdx.x] = m * (1.0f/512.0f);
    }
    __syncthreads();
    if (threadIdx.x < 32){
        int j = threadIdx.x;
        float t = 0.f;
        for (int ff=0; ff<32; ff++) t += smean[ff]*attW[ff*32 + j];
        ctx[b*32 + j] = tanhf(t);
    }
}

// attention phase 2: p = Σ_n af_n * sigmoid(af_n · ctx)
__device__ __forceinline__ void att2_body(int side, int b){
    const float* af  = side ? g_af2  : g_af1;
    const float* ctx = side ? g_ctx2 : g_ctx1;
    float* gp        = side ? g_p2   : g_p1;
    __shared__ float st[32];
    __shared__ float ssig[NPG];
    __shared__ float sm2[8*32];
    if (threadIdx.x < 32) st[threadIdx.x] = ctx[b*32 + threadIdx.x];
    __syncthreads();
    const float* base = af + (size_t)b*NPG*32;
    for (int n = threadIdx.x; n < NPG; n += 256){
        float d = 0.f;
        #pragma unroll
        for (int q=0; q<8; q++){
            float4 v = *(const float4*)(base + n*32 + q*4);
            d += v.x*st[q*4] + v.y*st[q*4+1] + v.z*st[q*4+2] + v.w*st[q*4+3];
        }
        ssig[n] = 1.0f/(1.0f + __expf(-d));
    }
    __syncthreads();
    int f = threadIdx.x & 31, grp = threadIdx.x >> 5;
    float acc = 0.f;
    for (int n = grp; n < NPG; n += 8) acc += base[n*32 + f] * ssig[n];
    sm2[grp*32 + f] = acc;
    __syncthreads();
    if (threadIdx.x < 32){
        float s = 0.f;
        for (int g=0; g<8; g++) s += sm2[g*32 + threadIdx.x];
        gp[b*32 + threadIdx.x] = s;
    }
}

// pass A: fp16 dot min/max (blocks < DOT_BLOCKS) + attention phase 1 (rest)
__global__ void __launch_bounds__(256) k_dotA_att(const float* __restrict__ attW){
    if (blockIdx.x >= DOT_BLOCKS){
        int q = blockIdx.x - DOT_BLOCKS;
        att1_body(q >> 7, q & (BGR-1), attW);
        return;
    }
    using namespace nvcuda;
    __shared__ __align__(16) __half sA[128*LDH];
    __shared__ __align__(16) __half sB[128*LDH];
    int b    = blockIdx.x >> 4;
    int tile = blockIdx.x & 15;
    int i0 = (tile >> 2) * 128, j0 = (tile & 3) * 128;
    stage_half_tiles(sA, sB,
                     g_af1 + ((size_t)b*NPG + i0)*32,
                     g_af2 + ((size_t)b*NPG + j0)*32);
    __syncthreads();

    int warp = threadIdx.x >> 5;
    float lmin = INFINITY, lmax = -INFINITY;

    #pragma unroll
    for (int tc = 0; tc < 8; tc++){
        wmma::fragment<wmma::accumulator, 16, 16, 16, float> c;
        wmma::fill_fragment(c, 0.0f);
        #pragma unroll
        for (int k0 = 0; k0 < 32; k0 += 16){
            wmma::fragment<wmma::matrix_a, 16, 16, 16, __half, wmma::row_major> a;
            wmma::fragment<wmma::matrix_b, 16, 16, 16, __half, wmma::col_major> bf;
            wmma::load_matrix_sync(a,  sA + warp*16*LDH + k0, LDH);
            wmma::load_matrix_sync(bf, sB + tc*16*LDH  + k0, LDH);
            wmma::mma_sync(c, a, bf, c);
        }
        #pragma unroll
        for (int q = 0; q < c.num_elements; q++){
            lmin = fminf(lmin, c.x[q]); lmax = fmaxf(lmax, c.x[q]);
        }
    }

    #pragma unroll
    for (int off=16; off; off>>=1){
        lmin = fminf(lmin, __shfl_down_sync(0xffffffffu, lmin, off));
        lmax = fmaxf(lmax, __shfl_down_sync(0xffffffffu, lmax, off));
    }
    __shared__ float wmn[8], wmx[8];
    if ((threadIdx.x & 31) == 0){ wmn[warp] = lmin; wmx[warp] = lmax; }
    __syncthreads();
    if (threadIdx.x == 0){
        float m = wmn[0], M = wmx[0];
        for (int q=1;q<8;q++){ m = fminf(m, wmn[q]); M = fmaxf(M, wmx[q]); }
        atomicMin(&g_minu[b], f2o(m));
        atomicMax(&g_maxu[b], f2o(M));
    }
}

// pass B: recompute identical fp16 dots + bin (blocks < DOT_BLOCKS) + att2
__global__ void __launch_bounds__(256) k_dotB_att(){
    if (blockIdx.x >= DOT_BLOCKS){
        int q = blockIdx.x - DOT_BLOCKS;
        att2_body(q >> 7, q & (BGR-1));
        return;
    }
    using namespace nvcuda;
    __shared__ __align__(16) __half sA[128*LDH];
    __shared__ __align__(16) __half sB[128*LDH];
    __shared__ float sth[15];
    __shared__ float scnt[15];
    int b    = blockIdx.x >> 4;
    int tile = blockIdx.x & 15;
    int i0 = (tile >> 2) * 128, j0 = (tile & 3) * 128;
    stage_half_tiles(sA, sB,
                     g_af1 + ((size_t)b*NPG + i0)*32,
                     g_af2 + ((size_t)b*NPG + j0)*32);
    if (threadIdx.x < 15){
        scnt[threadIdx.x] = 0.f;
        float tmin = o2f(g_minu[b]), tmax = o2f(g_maxu[b]);
        float mn = 1.0f/(1.0f + expf(-tmin));
        float mx = 1.0f/(1.0f + expf(-tmax));
        float rng = (mx > mn) ? (mx - mn) : 1.0f;
        const float PINF = __int_as_float(0x7f800000);
        float p = mn + rng * ((threadIdx.x + 1) * (1.0f/16.0f));
        float thr;
        if (p <= 0.0f)      thr = -PINF;
        else if (p >= 1.0f) thr =  PINF;
        else                thr = logf(p / (1.0f - p));
        sth[threadIdx.x] = thr;
    }
    __syncthreads();

    float th[15];
    #pragma unroll
    for (int k=0;k<15;k++) th[k] = sth[k];

    int warp = threadIdx.x >> 5;
    float cnt[15] = {};

    #pragma unroll
    for (int tc = 0; tc < 8; tc++){
        wmma::fragment<wmma::accumulator, 16, 16, 16, float> c;
        wmma::fill_fragment(c, 0.0f);
        #pragma unroll
        for (int k0 = 0; k0 < 32; k0 += 16){
            wmma::fragment<wmma::matrix_a, 16, 16, 16, __half, wmma::row_major> a;
            wmma::fragment<wmma::matrix_b, 16, 16, 16, __half, wmma::col_major> bf;
            wmma::load_matrix_sync(a,  sA + warp*16*LDH + k0, LDH);
            wmma::load_matrix_sync(bf, sB + tc*16*LDH  + k0, LDH);
            wmma::mma_sync(c, a, bf, c);
        }
        #pragma unroll
        for (int q = 0; q < c.num_elements; q++){
            float v = c.x[q];
            #pragma unroll
            for (int k=0;k<15;k++)
                cnt[k] += (v >= th[k]) ? 1.0f : 0.0f;
        }
    }

    #pragma unroll
    for (int off=16; off; off>>=1)
        #pragma unroll
        for (int k=0;k<15;k++)
            cnt[k] += __shfl_down_sync(0xffffffffu, cnt[k], off);
    if ((threadIdx.x & 31) == 0)
        #pragma unroll
        for (int k=0;k<15;k++)
            atomicAdd(&scnt[k], cnt[k]);
    __syncthreads();
    if (threadIdx.x < 15)
        atomicAdd(&g_hist[b*NBINS + threadIdx.x + 1], scnt[threadIdx.x]);
}

// ---------------- NTN + head -----------------------------------------------
__global__ void __launch_bounds__(512) k_ntn(const float* __restrict__ ntnW,
                                             const float* __restrict__ ntnV,
                                             const float* __restrict__ ntnb,
                                             const float* __restrict__ fc1W,
                                             const float* __restrict__ fc1b,
                                             const float* __restrict__ scW,
                                             const float* __restrict__ scb,
                                             float* __restrict__ out){
    int b = blockIdx.x;
    __shared__ float sp1[32], sp2[32], sred[512], sfeat[32], sh[16];
    int tid = threadIdx.x;
    if (tid < 32){ sp1[tid] = g_p1[b*32+tid]; sp2[tid] = g_p2[b*32+tid]; }
    __syncthreads();
    int j = tid >> 4, k = tid & 15;
    float acc = 0.f;
    #pragma unroll 8
    for (int i=0; i<32; i++) acc += sp1[i] * ntnW[i*512 + j*16 + k];
    sred[tid] = acc * sp2[j];
    __syncthreads();
    for (int off=256; off>=16; off>>=1){
        if (tid < off) sred[tid] += sred[tid+off];
        __syncthreads();
    }
    if (tid < 16){
        float blk = 0.f;
        for (int i=0; i<32; i++)
            blk += sp1[i]*ntnV[tid*64 + i] + sp2[i]*ntnV[tid*64 + 32 + i];
        sfeat[tid] = fmaxf(sred[tid] + blk + ntnb[tid], 0.f);
        float ck  = (tid==0)  ? 262144.0f : g_hist[b*NBINS + tid];
        float ck1 = (tid==15) ? 0.0f      : g_hist[b*NBINS + tid + 1];
        sfeat[16 + tid] = (ck - ck1) * (1.0f/262144.0f);
    }
    __syncthreads();
    if (tid < 16){
        float h = fc1b[tid];
        for (int m=0; m<32; m++) h += sfeat[m]*fc1W[m*16 + tid];
        sh[tid] = fmaxf(h, 0.f);
    }
    __syncthreads();
    if (tid == 0){
        float o = scb[0];
        for (int n=0; n<16; n++) o += sh[n]*scW[n];
        out[b] = 1.0f/(1.0f + expf(-o));
    }
}

// ---------------- launch ----------------------------------------------------
extern "C" void kernel_launch(void* const* d_in, const int* in_sizes, int n_in,
                              void* d_out, int out_size) {
    const float* x1   = (const float*)d_in[0];
    const float* x2   = (const float*)d_in[1];
    const int*   ei1  = (const int*)d_in[2];
    const int*   ei2  = (const int*)d_in[3];
    const float* W1   = (const float*)d_in[6];
    const float* b1   = (const float*)d_in[7];
    const float* W2   = (const float*)d_in[8];
    const float* b2   = (const float*)d_in[9];
    const float* W3   = (const float*)d_in[10];
    const float* b3   = (const float*)d_in[11];
    const float* attW = (const float*)d_in[12];
    const float* ntnW = (const float*)d_in[13];
    const float* ntnV = (const float*)d_in[14];
    const float* ntnb = (const float*)d_in[15];
    const float* fc1W = (const float*)d_in[16];
    const float* fc1b = (const float*)d_in[17];
    const float* scW  = (const float*)d_in[18];
    const float* scb  = (const float*)d_in[19];
    float* out = (float*)d_out;
    int E = in_sizes[2] / 2;

    // CSR build, both sides fused (k_count also inits histogram state)
    k_count<<<dim3((E+255)/256, 2), 256>>>(ei1, ei2, E);
    k_scan1<<<dim3(256, 2), 256>>>();
    k_scan2<<<2, 256>>>();
    k_scan3<<<dim3(TOT/256, 2), 256>>>(E);
    k_fill<<<dim3((E+255)/256, 2), 256>>>(ei1, ei2, E);

    // GCN stack, both sides fused (fp16 wmma GEMM; h0/h1 fp16)
    k_gemm<128,64><<<dim3(TOT/32, 2), 256>>>(x1, x2, W1, 0);
    k_gf<64,true,false><<<dim3(TOT*8/256, 2), 256>>>(b1);

    k_gemm<64,64><<<dim3(TOT/32, 2), 256>>>(nullptr, nullptr, W2, 1);
    k_gf<64,true,false><<<dim3(TOT*8/256, 2), 256>>>(b2);

    k_gemm<64,32><<<dim3(TOT/64, 2), 256>>>(nullptr, nullptr, W3, 1);
    k_gf<32,false,true><<<dim3(TOT*4/256, 2), 256>>>(b3);

    // histogram + attention fused (dotA+att1, then dotB+att2)
    k_dotA_att<<<DOT_BLOCKS + 2*BGR, 256>>>(attW);
    k_dotB_att<<<DOT_BLOCKS + 2*BGR, 256>>>();

    k_ntn<<<BGR, 512>>>(ntnW, ntnV, ntnb, fc1W, fc1b, scW, scb, out);
}

// round 17
// speedup vs baseline: 1.0440x; 1.0287x over previous
#include <cuda_runtime.h>
#include <cuda_fp16.h>
#include <math.h>
#include <mma.h>

#define TOT 65536
#define BGR 128
#define NPG 512
#define NBINS 16
#define EDG 1048576   // 16*TOT

// ---------------- scratch (__device__ globals; zero-init at load) ----------
// side 1
__device__ int    g_cnt1[TOT];          // zero-maintained
__device__ int    g_start1[TOT+1];
__device__ int    g_cursor1[TOT];
__device__ int    g_bsum1[256];
__device__ int    g_boff1[256];
__device__ int    g_srcs1[EDG];
__device__ float  g_dis1[TOT];
__device__ __half g_h0a[TOT*64];
__device__ __half g_h1a[TOT*64];
// side 2
__device__ int    g_cnt2[TOT];          // zero-maintained
__device__ int    g_start2[TOT+1];
__device__ int    g_cursor2[TOT];
__device__ int    g_bsum2[256];
__device__ int    g_boff2[256];
__device__ int    g_srcs2[EDG];
__device__ float  g_dis2[TOT];
__device__ __half g_h0b[TOT*64];
__device__ __half g_h1b[TOT*64];
// shared tail
__device__ float g_af1[TOT*32];
__device__ float g_af2[TOT*32];
__device__ unsigned g_minu[BGR];
__device__ unsigned g_maxu[BGR];
__device__ float g_hist[BGR*NBINS];     // slots 1..15 = cumulative counts
__device__ float g_ctx1[BGR*32];
__device__ float g_ctx2[BGR*32];
__device__ float g_p1[BGR*32];
__device__ float g_p2[BGR*32];

// ---------------- helpers ---------------------------------------------------
__device__ __forceinline__ unsigned f2o(float f){
    unsigned u = __float_as_uint(f);
    return (u & 0x80000000u) ? ~u : (u | 0x80000000u);
}
__device__ __forceinline__ float o2f(unsigned u){
    return __uint_as_float((u & 0x80000000u) ? (u & 0x7fffffffu) : ~u);
}
// accumulate 8 halves (packed in uint4) into acc[0..7]
__device__ __forceinline__ void add8(float* acc, uint4 v){
    __half2 h; float2 f;
    *(unsigned*)&h = v.x; f = __half22float2(h); acc[0]+=f.x; acc[1]+=f.y;
    *(unsigned*)&h = v.y; f = __half22float2(h); acc[2]+=f.x; acc[3]+=f.y;
    *(unsigned*)&h = v.z; f = __half22float2(h); acc[4]+=f.x; acc[5]+=f.y;
    *(unsigned*)&h = v.w; f = __half22float2(h); acc[6]+=f.x; acc[7]+=f.y;
}
// pack 8 floats (two float4) into uint4 of halves
__device__ __forceinline__ uint4 pack8(float4 v0, float4 v1){
    __half2 ha = __floats2half2_rn(v0.x, v0.y);
    __half2 hb = __floats2half2_rn(v0.z, v0.w);
    __half2 hc = __floats2half2_rn(v1.x, v1.y);
    __half2 hd = __floats2half2_rn(v1.z, v1.w);
    uint4 u;
    u.x = *(unsigned*)&ha; u.y = *(unsigned*)&hb;
    u.z = *(unsigned*)&hc; u.w = *(unsigned*)&hd;
    return u;
}

// ---------------- CSR build (both sides fused via blockIdx.y) ---------------
__global__ void k_count(const int* __restrict__ ei1, const int* __restrict__ ei2,
                        int E){
    int side = blockIdx.y;
    if (blockIdx.x == 0 && side == 0){
        if (threadIdx.x < BGR){ g_minu[threadIdx.x] = 0xFFFFFFFFu; g_maxu[threadIdx.x] = 0u; }
        #pragma unroll
        for (int q = 0; q < (BGR*NBINS)/256; q++)
            g_hist[q*256 + threadIdx.x] = 0.f;
    }
    const int* dst = (side ? ei2 : ei1) + E;
    int* cnt = side ? g_cnt2 : g_cnt1;
    int i = blockIdx.x*256 + threadIdx.x;
    if (i < E) atomicAdd(&cnt[dst[i]], 1);
}

__global__ void k_scan1(){
    int side = blockIdx.y;
    const int* cnt = side ? g_cnt2 : g_cnt1;
    int* start = side ? g_start2 : g_start1;
    int* bsum  = side ? g_bsum2  : g_bsum1;
    __shared__ int s[256];
    int i = blockIdx.x*256 + threadIdx.x;
    int c = cnt[i];
    s[threadIdx.x] = c;
    __syncthreads();
    #pragma unroll
    for (int off = 1; off < 256; off <<= 1){
        int t = (threadIdx.x >= off) ? s[threadIdx.x - off] : 0;
        __syncthreads();
        s[threadIdx.x] += t;
        __syncthreads();
    }
    start[i] = s[threadIdx.x] - c;
    if (threadIdx.x == 255) bsum[blockIdx.x] = s[255];
}

__global__ void k_scan2(){
    int side = blockIdx.x;
    const int* bsum = side ? g_bsum2 : g_bsum1;
    int* boff       = side ? g_boff2 : g_boff1;
    __shared__ int s[256];
    int c = bsum[threadIdx.x];
    s[threadIdx.x] = c;
    __syncthreads();
    #pragma unroll
    for (int off = 1; off < 256; off <<= 1){
        int t = (threadIdx.x >= off) ? s[threadIdx.x - off] : 0;
        __syncthreads();
        s[threadIdx.x] += t;
        __syncthreads();
    }
    boff[threadIdx.x] = s[threadIdx.x] - c;
}

__global__ void k_scan3(int E){
    int side = blockIdx.y;
    int* cnt    = side ? g_cnt2    : g_cnt1;
    int* start  = side ? g_start2  : g_start1;
    int* cursor = side ? g_cursor2 : g_cursor1;
    const int* boff = side ? g_boff2 : g_boff1;
    float* dis  = side ? g_dis2    : g_dis1;
    int i = blockIdx.x*256 + threadIdx.x;
    int st = start[i] + boff[i >> 8];
    start[i]  = st;
    cursor[i] = st;
    float d = (float)cnt[i] + 1.0f;
    dis[i] = rsqrtf(d);
    cnt[i] = 0;                              // restore zero invariant
    if (i == 0) start[TOT] = E;
}

// ------ layer-1 GEMM (fp16 wmma) + CSR fill fused as heterogeneous blocks ---
// blocks [0, TOT/32): GEMM K=128,M=64 ; blocks [TOT/32, ...): fill chunks.
#define G1_BLOCKS (TOT/32)
__global__ void __launch_bounds__(256) k_gemm1_fill(const float* __restrict__ Xa,
                                                    const float* __restrict__ Xb,
                                                    const float* __restrict__ W,
                                                    const int* __restrict__ ei1,
                                                    const int* __restrict__ ei2,
                                                    int E){
    using namespace nvcuda;
    constexpr int K = 128, M = 64;
    constexpr int R   = 32;
    constexpr int CT  = M / 16;
    constexpr int KP2 = 72;
    constexpr int MP2 = M + 8;
    __shared__ __align__(16) __half sX[R * KP2];
    __shared__ __align__(16) __half sW[64 * MP2];
    __shared__ __align__(16) float  sO[2048];

    int side = blockIdx.y;

    if (blockIdx.x >= G1_BLOCKS){
        // ---- fill role ----
        const int* ei = side ? ei2 : ei1;
        const int* src = ei;
        const int* dst = ei + E;
        int* cursor = side ? g_cursor2 : g_cursor1;
        int* srcs   = side ? g_srcs2   : g_srcs1;
        int i = (blockIdx.x - G1_BLOCKS)*256 + threadIdx.x;
        if (i < E){
            int d = dst[i];
            int pos = atomicAdd(&cursor[d], 1);
            srcs[pos] = src[i];
        }
        return;
    }

    // ---- GEMM role ----
    const float* dis = side ? g_dis2 : g_dis1;
    __half* H0       = side ? g_h0b  : g_h0a;
    const float* Xf  = side ? Xb : Xa;

    int row0 = blockIdx.x * R;
    int warp = threadIdx.x >> 5;
    int tr = warp / CT, tc = warp % CT;

    wmma::fragment<wmma::accumulator, 16, 16, 16, float> c;
    wmma::fill_fragment(c, 0.0f);

    for (int kc = 0; kc < K; kc += 64){
        for (int i = threadIdx.x; i < R*8; i += 256){
            int r = i >> 3, cc = i & 7;
            const float4* p = (const float4*)(Xf + (size_t)(row0 + r)*K + kc + cc*8);
            *(uint4*)(sX + r*KP2 + cc*8) = pack8(p[0], p[1]);
        }
        for (int i = threadIdx.x; i < 64*(M/8); i += 256){
            int r = i / (M/8), cc = i % (M/8);
            const float4* p = (const float4*)(W + (size_t)(kc + r)*M + cc*8);
            *(uint4*)(sW + r*MP2 + cc*8) = pack8(p[0], p[1]);
        }
        __syncthreads();
        #pragma unroll
        for (int k0 = 0; k0 < 64; k0 += 16){
            wmma::fragment<wmma::matrix_a, 16, 16, 16, __half, wmma::row_major> a;
            wmma::fragment<wmma::matrix_b, 16, 16, 16, __half, wmma::row_major> bf;
            wmma::load_matrix_sync(a,  sX + tr*16*KP2 + k0, KP2);
            wmma::load_matrix_sync(bf, sW + k0*MP2 + tc*16, MP2);
            wmma::mma_sync(c, a, bf, c);
        }
        __syncthreads();
    }

    wmma::store_matrix_sync(sO + tr*16*M + tc*16, c, M, wmma::mem_row_major);
    __syncthreads();
    constexpr int MH = M / 8;
    for (int i = threadIdx.x; i < R * MH; i += 256){
        int r = i / MH;
        float d = dis[row0 + r];
        float4 v0 = ((float4*)sO)[i*2];
        float4 v1 = ((float4*)sO)[i*2 + 1];
        v0.x*=d; v0.y*=d; v0.z*=d; v0.w*=d;
        v1.x*=d; v1.y*=d; v1.z*=d; v1.w*=d;
        ((uint4*)(H0 + (size_t)row0 * M))[i] = pack8(v0, v1);
    }
}

// ------ dense GEMM via fp16 wmma (layers 2/3): X fp16 = g_h1a/g_h1b ---------
template<int K, int M>
__global__ void __launch_bounds__(256) k_gemm(const float* __restrict__ W){
    using namespace nvcuda;
    constexpr int R   = 2048 / M;
    constexpr int CT  = M / 16;
    constexpr int KP2 = 72;
    constexpr int MP2 = M + 8;
    __shared__ __align__(16) __half sX[R * KP2];
    __shared__ __align__(16) __half sW[64 * MP2];
    __shared__ __align__(16) float  sO[2048];

    int side = blockIdx.y;
    const float* dis = side ? g_dis2 : g_dis1;
    __half* H0       = side ? g_h0b  : g_h0a;
    const __half* Xh = side ? g_h1b : g_h1a;

    int row0 = blockIdx.x * R;
    int warp = threadIdx.x >> 5;
    int tr = warp / CT, tc = warp % CT;

    wmma::fragment<wmma::accumulator, 16, 16, 16, float> c;
    wmma::fill_fragment(c, 0.0f);

    for (int i = threadIdx.x; i < R*8; i += 256){
        int r = i >> 3, cc = i & 7;
        *(uint4*)(sX + r*KP2 + cc*8) =
            ((const uint4*)(Xh + (size_t)(row0 + r) * K))[cc];
    }
    for (int i = threadIdx.x; i < 64*(M/8); i += 256){
        int r = i / (M/8), cc = i % (M/8);
        const float4* p = (const float4*)(W + (size_t)r*M + cc*8);
        *(uint4*)(sW + r*MP2 + cc*8) = pack8(p[0], p[1]);
    }
    __syncthreads();
    #pragma unroll
    for (int k0 = 0; k0 < 64; k0 += 16){
        wmma::fragment<wmma::matrix_a, 16, 16, 16, __half, wmma::row_major> a;
        wmma::fragment<wmma::matrix_b, 16, 16, 16, __half, wmma::row_major> bf;
        wmma::load_matrix_sync(a,  sX + tr*16*KP2 + k0, KP2);
        wmma::load_matrix_sync(bf, sW + k0*MP2 + tc*16, MP2);
        wmma::mma_sync(c, a, bf, c);
    }
    __syncthreads();

    wmma::store_matrix_sync(sO + tr*16*M + tc*16, c, M, wmma::mem_row_major);
    __syncthreads();
    constexpr int MH = M / 8;
    for (int i = threadIdx.x; i < R * MH; i += 256){
        int r = i / MH;
        float d = dis[row0 + r];
        float4 v0 = ((float4*)sO)[i*2];
        float4 v1 = ((float4*)sO)[i*2 + 1];
        v0.x*=d; v0.y*=d; v0.z*=d; v0.w*=d;
        v1.x*=d; v1.y*=d; v1.z*=d; v1.w*=d;
        ((uint4*)(H0 + (size_t)row0 * M))[i] = pack8(v0, v1);
    }
}

// ------ fused gather+finalize, both sides: out = relu?((Σ+self)*dis + b) ----
template<int F, bool RELU, bool LAST>
__global__ void __launch_bounds__(256) k_gf(const float* __restrict__ bias){
    constexpr int G  = F/8;
    constexpr int SH = (F==64) ? 3 : 2;
    int side = blockIdx.y;
    const __half* h0  = side ? g_h0b    : g_h0a;
    const int* srcs   = side ? g_srcs2  : g_srcs1;
    const int* start  = side ? g_start2 : g_start1;
    const float* dis  = side ? g_dis2   : g_dis1;

    int t   = blockIdx.x*256 + threadIdx.x;
    int row = t >> SH;
    int j   = t & (G-1);

    float acc[8] = {};
    add8(acc, ((const uint4*)(h0 + (size_t)row*F))[j]);      // self term

    int e  = start[row];
    int e1 = start[row+1];
    for (; e + 1 < e1; e += 2){
        int sa = __ldg(&srcs[e]);
        int sb = __ldg(&srcs[e+1]);
        uint4 va = ((const uint4*)(h0 + (size_t)sa*F))[j];
        uint4 vb = ((const uint4*)(h0 + (size_t)sb*F))[j];
        add8(acc, va);
        add8(acc, vb);
    }
    if (e < e1){
        int sa = __ldg(&srcs[e]);
        add8(acc, ((const uint4*)(h0 + (size_t)sa*F))[j]);
    }

    float di = dis[row];
    float4 b0 = ((const float4*)bias)[2*j];
    float4 b1 = ((const float4*)bias)[2*j + 1];
    float4 o0, o1;
    o0.x = acc[0]*di + b0.x; o0.y = acc[1]*di + b0.y;
    o0.z = acc[2]*di + b0.z; o0.w = acc[3]*di + b0.w;
    o1.x = acc[4]*di + b1.x; o1.y = acc[5]*di + b1.y;
    o1.z = acc[6]*di + b1.z; o1.w = acc[7]*di + b1.w;
    if (RELU){
        o0.x = fmaxf(o0.x,0.f); o0.y = fmaxf(o0.y,0.f);
        o0.z = fmaxf(o0.z,0.f); o0.w = fmaxf(o0.w,0.f);
        o1.x = fmaxf(o1.x,0.f); o1.y = fmaxf(o1.y,0.f);
        o1.z = fmaxf(o1.z,0.f); o1.w = fmaxf(o1.w,0.f);
    }
    if (LAST){
        float* out = side ? g_af2 : g_af1;
        ((float4*)out)[2*t]     = o0;
        ((float4*)out)[2*t + 1] = o1;
    } else {
        __half* out = side ? g_h1b : g_h1a;
        ((uint4*)out)[t] = pack8(o0, o1);
    }
}

// ---------------- histogram + attention (fused heterogeneous launches) ------
#define LDH 40   // halves; 80-byte row stride, 16B aligned
#define DOT_BLOCKS (BGR*16)

__device__ __forceinline__ void stage_half_tiles(__half* sA, __half* sB,
                                                 const float* A, const float* Bp){
    for (int i = threadIdx.x; i < 128*4; i += 256){
        int r = i >> 2, c4 = i & 3;
        const float4* pa = (const float4*)(A + (size_t)r*32);
        *(uint4*)(sA + r*LDH + c4*8) = pack8(pa[c4*2], pa[c4*2 + 1]);
        const float4* pb = (const float4*)(Bp + (size_t)r*32);
        *(uint4*)(sB + r*LDH + c4*8) = pack8(pb[c4*2], pb[c4*2 + 1]);
    }
}

// attention phase 1: ctx = tanh(mean(af) @ attW)
__device__ __forceinline__ void att1_body(int side, int b,
                                          const float* __restrict__ attW){
    const float* af = side ? g_af2  : g_af1;
    float* ctx      = side ? g_ctx2 : g_ctx1;
    __shared__ float sm[8*32], smean[32];
    int f = threadIdx.x & 31, grp = threadIdx.x >> 5;
    const float* base = af + (size_t)b*NPG*32;
    float acc = 0.f;
    for (int n = grp; n < NPG; n += 8) acc += base[n*32 + f];
    sm[grp*32 + f] = acc;
    __syncthreads();
    if (threadIdx.x < 32){
        float m = 0.f;
        for (int g=0; g<8; g++) m += sm[g*32 + threadIdx.x];
        smean[threadIdx.x] = m * (1.0f/512.0f);
    }
    __syncthreads();
    if (threadIdx.x < 32){
        int j = threadIdx.x;
        float t = 0.f;
        for (int ff=0; ff<32; ff++) t += smean[ff]*attW[ff*32 + j];
        ctx[b*32 + j] = tanhf(t);
    }
}

// attention phase 2: p = Σ_n af_n * sigmoid(af_n · ctx)
__device__ __forceinline__ void att2_body(int side, int b){
    const float* af  = side ? g_af2  : g_af1;
    const float* ctx = side ? g_ctx2 : g_ctx1;
    float* gp        = side ? g_p2   : g_p1;
    __shared__ float st[32];
    __shared__ float ssig[NPG];
    __shared__ float sm2[8*32];
    if (threadIdx.x < 32) st[threadIdx.x] = ctx[b*32 + threadIdx.x];
    __syncthreads();
    const float* base = af + (size_t)b*NPG*32;
    for (int n = threadIdx.x; n < NPG; n += 256){
        float d = 0.f;
        #pragma unroll
        for (int q=0; q<8; q++){
            float4 v = *(const float4*)(base + n*32 + q*4);
            d += v.x*st[q*4] + v.y*st[q*4+1] + v.z*st[q*4+2] + v.w*st[q*4+3];
        }
        ssig[n] = 1.0f/(1.0f + __expf(-d));
    }
    __syncthreads();
    int f = threadIdx.x & 31, grp = threadIdx.x >> 5;
    float acc = 0.f;
    for (int n = grp; n < NPG; n += 8) acc += base[n*32 + f] * ssig[n];
    sm2[grp*32 + f] = acc;
    __syncthreads();
    if (threadIdx.x < 32){
        float s = 0.f;
        for (int g=0; g<8; g++) s += sm2[g*32 + threadIdx.x];
        gp[b*32 + threadIdx.x] = s;
    }
}

// pass A: fp16 dot min/max (blocks < DOT_BLOCKS) + attention phase 1 (rest)
__global__ void __launch_bounds__(256) k_dotA_att(const float* __restrict__ attW){
    if (blockIdx.x >= DOT_BLOCKS){
        int q = blockIdx.x - DOT_BLOCKS;
        att1_body(q >> 7, q & (BGR-1), attW);
        return;
    }
    using namespace nvcuda;
    __shared__ __align__(16) __half sA[128*LDH];
    __shared__ __align__(16) __half sB[128*LDH];
    int b    = blockIdx.x >> 4;
    int tile = blockIdx.x & 15;
    int i0 = (tile >> 2) * 128, j0 = (tile & 3) * 128;
    stage_half_tiles(sA, sB,
                     g_af1 + ((size_t)b*NPG + i0)*32,
                     g_af2 + ((size_t)b*NPG + j0)*32);
    __syncthreads();

    int warp = threadIdx.x >> 5;
    float lmin = INFINITY, lmax = -INFINITY;

    #pragma unroll
    for (int tc = 0; tc < 8; tc++){
        wmma::fragment<wmma::accumulator, 16, 16, 16, float> c;
        wmma::fill_fragment(c, 0.0f);
        #pragma unroll
        for (int k0 = 0; k0 < 32; k0 += 16){
            wmma::fragment<wmma::matrix_a, 16, 16, 16, __half, wmma::row_major> a;
            wmma::fragment<wmma::matrix_b, 16, 16, 16, __half, wmma::col_major> bf;
            wmma::load_matrix_sync(a,  sA + warp*16*LDH + k0, LDH);
            wmma::load_matrix_sync(bf, sB + tc*16*LDH  + k0, LDH);
            wmma::mma_sync(c, a, bf, c);
        }
        #pragma unroll
        for (int q = 0; q < c.num_elements; q++){
            lmin = fminf(lmin, c.x[q]); lmax = fmaxf(lmax, c.x[q]);
        }
    }

    #pragma unroll
    for (int off=16; off; off>>=1){
        lmin = fminf(lmin, __shfl_down_sync(0xffffffffu, lmin, off));
        lmax = fmaxf(lmax, __shfl_down_sync(0xffffffffu, lmax, off));
    }
    __shared__ float wmn[8], wmx[8];
    if ((threadIdx.x & 31) == 0){ wmn[warp] = lmin; wmx[warp] = lmax; }
    __syncthreads();
    if (threadIdx.x == 0){
        float m = wmn[0], M = wmx[0];
        for (int q=1;q<8;q++){ m = fminf(m, wmn[q]); M = fmaxf(M, wmx[q]); }
        atomicMin(&g_minu[b], f2o(m));
        atomicMax(&g_maxu[b], f2o(M));
    }
}

// pass B: recompute identical fp16 dots + bin (blocks < DOT_BLOCKS) + att2
__global__ void __launch_bounds__(256) k_dotB_att(){
    if (blockIdx.x >= DOT_BLOCKS){
        int q = blockIdx.x - DOT_BLOCKS;
        att2_body(q >> 7, q & (BGR-1));
        return;
    }
    using namespace nvcuda;
    __shared__ __align__(16) __half sA[128*LDH];
    __shared__ __align__(16) __half sB[128*LDH];
    __shared__ float sth[15];
    __shared__ float scnt[15];
    int b    = blockIdx.x >> 4;
    int tile = blockIdx.x & 15;
    int i0 = (tile >> 2) * 128, j0 = (tile & 3) * 128;
    stage_half_tiles(sA, sB,
                     g_af1 + ((size_t)b*NPG + i0)*32,
                     g_af2 + ((size_t)b*NPG + j0)*32);
    if (threadIdx.x < 15){
        scnt[threadIdx.x] = 0.f;
        float tmin = o2f(g_minu[b]), tmax = o2f(g_maxu[b]);
        float mn = 1.0f/(1.0f + expf(-tmin));
        float mx = 1.0f/(1.0f + expf(-tmax));
        float rng = (mx > mn) ? (mx - mn) : 1.0f;
        const float PINF = __int_as_float(0x7f800000);
        float p = mn + rng * ((threadIdx.x + 1) * (1.0f/16.0f));
        float thr;
        if (p <= 0.0f)      thr = -PINF;
        else if (p >= 1.0f) thr =  PINF;
        else                thr = logf(p / (1.0f - p));
        sth[threadIdx.x] = thr;
    }
    __syncthreads();

    float th[15];
    #pragma unroll
    for (int k=0;k<15;k++) th[k] = sth[k];

    int warp = threadIdx.x >> 5;
    float cnt[15] = {};

    #pragma unroll
    for (int tc = 0; tc < 8; tc++){
        wmma::fragment<wmma::accumulator, 16, 16, 16, float> c;
        wmma::fill_fragment(c, 0.0f);
        #pragma unroll
        for (int k0 = 0; k0 < 32; k0 += 16){
            wmma::fragment<wmma::matrix_a, 16, 16, 16, __half, wmma::row_major> a;
            wmma::fragment<wmma::matrix_b, 16, 16, 16, __half, wmma::col_major> bf;
            wmma::load_matrix_sync(a,  sA + warp*16*LDH + k0, LDH);
            wmma::load_matrix_sync(bf, sB + tc*16*LDH  + k0, LDH);
            wmma::mma_sync(c, a, bf, c);
        }
        #pragma unroll
        for (int q = 0; q < c.num_elements; q++){
            float v = c.x[q];
            #pragma unroll
            for (int k=0;k<15;k++)
                cnt[k] += (v >= th[k]) ? 1.0f : 0.0f;
        }
    }

    #pragma unroll
    for (int off=16; off; off>>=1)
        #pragma unroll
        for (int k=0;k<15;k++)
            cnt[k] += __shfl_down_sync(0xffffffffu, cnt[k], off);
    if ((threadIdx.x & 31) == 0)
        #pragma unroll
        for (int k=0;k<15;k++)
            atomicAdd(&scnt[k], cnt[k]);
    __syncthreads();
    if (threadIdx.x < 15)
        atomicAdd(&g_hist[b*NBINS + threadIdx.x + 1], scnt[threadIdx.x]);
}

// ---------------- NTN + head -----------------------------------------------
__global__ void __launch_bounds__(512) k_ntn(const float* __restrict__ ntnW,
                                             const float* __restrict__ ntnV,
                                             const float* __restrict__ ntnb,
                                             const float* __restrict__ fc1W,
                                             const float* __restrict__ fc1b,
                                             const float* __restrict__ scW,
                                             const float* __restrict__ scb,
                                             float* __restrict__ out){
    int b = blockIdx.x;
    __shared__ float sp1[32], sp2[32], sred[512], sfeat[32], sh[16];
    int tid = threadIdx.x;
    if (tid < 32){ sp1[tid] = g_p1[b*32+tid]; sp2[tid] = g_p2[b*32+tid]; }
    __syncthreads();
    int j = tid >> 4, k = tid & 15;
    float acc = 0.f;
    #pragma unroll 8
    for (int i=0; i<32; i++) acc += sp1[i] * ntnW[i*512 + j*16 + k];
    sred[tid] = acc * sp2[j];
    __syncthreads();
    for (int off=256; off>=16; off>>=1){
        if (tid < off) sred[tid] += sred[tid+off];
        __syncthreads();
    }
    if (tid < 16){
        float blk = 0.f;
        for (int i=0; i<32; i++)
            blk += sp1[i]*ntnV[tid*64 + i] + sp2[i]*ntnV[tid*64 + 32 + i];
        sfeat[tid] = fmaxf(sred[tid] + blk + ntnb[tid], 0.f);
        float ck  = (tid==0)  ? 262144.0f : g_hist[b*NBINS + tid];
        float ck1 = (tid==15) ? 0.0f      : g_hist[b*NBINS + tid + 1];
        sfeat[16 + tid] = (ck - ck1) * (1.0f/262144.0f);
    }
    __syncthreads();
    if (tid < 16){
        float h = fc1b[tid];
        for (int m=0; m<32; m++) h += sfeat[m]*fc1W[m*16 + tid];
        sh[tid] = fmaxf(h, 0.f);
    }
    __syncthreads();
    if (tid == 0){
        float o = scb[0];
        for (int n=0; n<16; n++) o += sh[n]*scW[n];
        out[b] = 1.0f/(1.0f + expf(-o));
    }
}

// ---------------- launch ----------------------------------------------------
extern "C" void kernel_launch(void* const* d_in, const int* in_sizes, int n_in,
                              void* d_out, int out_size) {
    const float* x1   = (const float*)d_in[0];
    const float* x2   = (const float*)d_in[1];
    const int*   ei1  = (const int*)d_in[2];
    const int*   ei2  = (const int*)d_in[3];
    const float* W1   = (const float*)d_in[6];
    const float* b1   = (const float*)d_in[7];
    const float* W2   = (const float*)d_in[8];
    const float* b2   = (const float*)d_in[9];
    const float* W3   = (const float*)d_in[10];
    const float* b3   = (const float*)d_in[11];
    const float* attW = (const float*)d_in[12];
    const float* ntnW = (const float*)d_in[13];
    const float* ntnV = (const float*)d_in[14];
    const float* ntnb = (const float*)d_in[15];
    const float* fc1W = (const float*)d_in[16];
    const float* fc1b = (const float*)d_in[17];
    const float* scW  = (const float*)d_in[18];
    const float* scb  = (const float*)d_in[19];
    float* out = (float*)d_out;
    int E = in_sizes[2] / 2;

    // CSR count + scans (k_count also inits histogram state)
    k_count<<<dim3((E+255)/256, 2), 256>>>(ei1, ei2, E);
    k_scan1<<<dim3(256, 2), 256>>>();
    k_scan2<<<2, 256>>>();
    k_scan3<<<dim3(TOT/256, 2), 256>>>(E);

    // layer-1 GEMM + CSR fill fused (independent after scans)
    k_gemm1_fill<<<dim3(G1_BLOCKS + (E+255)/256, 2), 256>>>(x1, x2, W1, ei1, ei2, E);
    k_gf<64,true,false><<<dim3(TOT*8/256, 2), 256>>>(b1);

    k_gemm<64,64><<<dim3(TOT/32, 2), 256>>>(W2);
    k_gf<64,true,false><<<dim3(TOT*8/256, 2), 256>>>(b2);

    k_gemm<64,32><<<dim3(TOT/64, 2), 256>>>(W3);
    k_gf<32,false,true><<<dim3(TOT*4/256, 2), 256>>>(b3);

    // histogram + attention fused (dotA+att1, then dotB+att2)
    k_dotA_att<<<DOT_BLOCKS + 2*BGR, 256>>>(attW);
    k_dotB_att<<<DOT_BLOCKS + 2*BGR, 256>>>();

    k_ntn<<<BGR, 512>>>(ntnW, ntnV, ntnb, fc1W, fc1b, scW, scb, out);
}